// round 4
// baseline (speedup 1.0000x reference)
#include <cuda_runtime.h>
#include <cstdint>

#define kB    32768
#define kT    276
#define kH    8
#define kK    4416      /* T*2H */
#define kN    276

__device__ float g_h[(size_t)kB * kK];   // scratch activations [B, T*2H]

// ---------------- Phase 1: bidirectional LSTM ----------------
__device__ __forceinline__ float sigm(float x) {
    return __fdividef(1.0f, 1.0f + __expf(-x));
}
__device__ __forceinline__ float tanh_acc(float x) {
    float e = __expf(-2.0f * fabsf(x));
    return copysignf(__fdividef(1.0f - e, 1.0f + e), x);
}

__global__ void __launch_bounds__(256) lstm_k(
    const float* __restrict__ x,
    const float* __restrict__ Wih_f, const float* __restrict__ Whh_f,
    const float* __restrict__ bih_f, const float* __restrict__ bhh_f,
    const float* __restrict__ Wih_b, const float* __restrict__ Whh_b,
    const float* __restrict__ bih_b, const float* __restrict__ bhh_b)
{
    __shared__ float s_whh[256], s_wih[64], s_b[32];
    const int tid = threadIdx.x;
    const int dir = blockIdx.y;
    const float* Whh = dir ? Whh_b : Whh_f;
    const float* Wih = dir ? Wih_b : Wih_f;
    s_whh[tid] = Whh[tid];
    if (tid < 64) s_wih[tid] = Wih[tid];
    if (tid < 32) s_b[tid] = (dir ? bih_b[tid] + bhh_b[tid] : bih_f[tid] + bhh_f[tid]);
    __syncthreads();

    const int b = blockIdx.x * 256 + tid;
    const float2* xp = reinterpret_cast<const float2*>(x) + (size_t)b * kT;
    int t = dir ? (kT - 1) : 0;
    const int dt = dir ? -1 : 1;
    float* hb = g_h + (size_t)b * kK + dir * 8;

    float h[8], c[8];
#pragma unroll
    for (int l = 0; l < 8; l++) { h[l] = 0.f; c[l] = 0.f; }

    float2 xv = xp[t];
    for (int s = 0; s < kT; ++s) {
        float2 xnext = xv;
        if (s + 1 < kT) xnext = xp[t + dt];
        float hn[8];
#pragma unroll
        for (int l = 0; l < 8; l++) {
            float ai = fmaf(xv.y, s_wih[2*l+1],      fmaf(xv.x, s_wih[2*l],      s_b[l]));
            float af = fmaf(xv.y, s_wih[2*(8+l)+1],  fmaf(xv.x, s_wih[2*(8+l)],  s_b[8+l]));
            float ag = fmaf(xv.y, s_wih[2*(16+l)+1], fmaf(xv.x, s_wih[2*(16+l)], s_b[16+l]));
            float ao = fmaf(xv.y, s_wih[2*(24+l)+1], fmaf(xv.x, s_wih[2*(24+l)], s_b[24+l]));
#pragma unroll
            for (int j = 0; j < 8; j++) {
                float hj = h[j];
                ai = fmaf(hj, s_whh[l*8+j],      ai);
                af = fmaf(hj, s_whh[(8+l)*8+j],  af);
                ag = fmaf(hj, s_whh[(16+l)*8+j], ag);
                ao = fmaf(hj, s_whh[(24+l)*8+j], ao);
            }
            float cn = fmaf(sigm(af), c[l], sigm(ai) * tanh_acc(ag));
            c[l] = cn;
            hn[l] = sigm(ao) * tanh_acc(cn);
        }
#pragma unroll
        for (int l = 0; l < 8; l++) h[l] = hn[l];
        float4* dst = reinterpret_cast<float4*>(hb + (size_t)t * 16);
        dst[0] = make_float4(hn[0], hn[1], hn[2], hn[3]);
        dst[1] = make_float4(hn[4], hn[5], hn[6], hn[7]);
        t += dt;
        xv = xnext;
    }
}

// ---------------- Phase 2: FC GEMM (fp32 FFMA, cp.async double-buffer) ----------------
// out[32768, 276] = g_h[32768, 4416] @ Wfc[276, 4416]^T + bfc
#define KC   16
#define NCH  (kK / KC)   /* 276 */
#define MT   64

__device__ __forceinline__ uint32_t smem_u32(const void* p) {
    uint32_t a;
    asm("{ .reg .u64 t; cvta.to.shared.u64 t, %1; cvt.u32.u64 %0, t; }" : "=r"(a) : "l"(p));
    return a;
}
__device__ __forceinline__ void cpa16(uint32_t d, const void* s) {
    asm volatile("cp.async.ca.shared.global [%0], [%1], 16;" :: "r"(d), "l"(s));
}
__device__ __forceinline__ void cpa4(uint32_t d, const void* s) {
    asm volatile("cp.async.ca.shared.global [%0], [%1], 4;" :: "r"(d), "l"(s));
}

__global__ void __launch_bounds__(256) fc_k(
    const float* __restrict__ Wfc, const float* __restrict__ bfc,
    float* __restrict__ out)
{
    __shared__ float sA[2][MT][KC];     // [m][k], broadcast reads
    __shared__ float sB[2][288][17];    // [n][k] pitch 17 -> conflict-free reads

    const int tid = threadIdx.x;
    const int tm  = tid >> 5;           // warp id 0..7 -> rows tm*8..tm*8+7
    const int tn  = tid & 31;           // lane -> cols tn + 32*j
    const size_t m0 = (size_t)blockIdx.x * MT;
    const float* Ab = g_h + m0 * kK;

    // zero B pad rows (n=276..287), both buffers
    if (tid < 204) {
        int n = 276 + tid / 17, k = tid % 17;
        sB[0][n][k] = 0.f; sB[1][n][k] = 0.f;
    }

    // chunk loaders
    auto loadA = [&](int ch, int buf) {
        int m = tid >> 2, kg = tid & 3;
        cpa16(smem_u32(&sA[buf][m][kg * 4]), Ab + (size_t)m * kK + ch * KC + kg * 4);
    };
    auto loadB = [&](int ch, int buf) {
#pragma unroll
        for (int it = 0; it < 18; it++) {
            int idx = tid + it * 256;
            if (idx < kN * KC) {
                int n = idx >> 4, k = idx & 15;
                cpa4(smem_u32(&sB[buf][n][k]), Wfc + (size_t)n * kK + ch * KC + k);
            }
        }
    };

    float acc[8][9];
#pragma unroll
    for (int i = 0; i < 8; i++)
#pragma unroll
        for (int j = 0; j < 9; j++) acc[i][j] = 0.f;

    loadA(0, 0); loadB(0, 0);
    asm volatile("cp.async.commit_group;");

    for (int ch = 0; ch < NCH; ch++) {
        const int cur = ch & 1;
        if (ch + 1 < NCH) {
            loadA(ch + 1, cur ^ 1); loadB(ch + 1, cur ^ 1);
            asm volatile("cp.async.commit_group;");
            asm volatile("cp.async.wait_group 1;");
        } else {
            asm volatile("cp.async.wait_group 0;");
        }
        __syncthreads();

#pragma unroll
        for (int k = 0; k < KC; k++) {
            float bb[9];
#pragma unroll
            for (int j = 0; j < 9; j++) bb[j] = sB[cur][tn + 32 * j][k];
#pragma unroll
            for (int i = 0; i < 8; i++) {
                float a = sA[cur][tm * 8 + i][k];
#pragma unroll
                for (int j = 0; j < 9; j++) acc[i][j] = fmaf(a, bb[j], acc[i][j]);
            }
        }
        __syncthreads();
    }

#pragma unroll
    for (int j = 0; j < 9; j++) {
        int n = tn + 32 * j;
        if (n < kN) {
            float bias = bfc[n];
#pragma unroll
            for (int i = 0; i < 8; i++)
                out[(m0 + tm * 8 + i) * kN + n] = acc[i][j] + bias;
        }
    }
}

extern "C" void kernel_launch(void* const* d_in, const int* in_sizes, int n_in,
                              void* d_out, int out_size) {
    const float* x     = (const float*)d_in[0];
    const float* Wih_f = (const float*)d_in[1];
    const float* Whh_f = (const float*)d_in[2];
    const float* bih_f = (const float*)d_in[3];
    const float* bhh_f = (const float*)d_in[4];
    const float* Wih_b = (const float*)d_in[5];
    const float* Whh_b = (const float*)d_in[6];
    const float* bih_b = (const float*)d_in[7];
    const float* bhh_b = (const float*)d_in[8];
    const float* Wfc   = (const float*)d_in[9];
    const float* bfc   = (const float*)d_in[10];
    float* out = (float*)d_out;

    lstm_k<<<dim3(kB / 256, 2), 256>>>(x, Wih_f, Whh_f, bih_f, bhh_f,
                                       Wih_b, Whh_b, bih_b, bhh_b);
    fc_k<<<kB / MT, 256>>>(Wfc, bfc, out);
}

// round 10
// speedup vs baseline: 2.5239x; 2.5239x over previous
#include <cuda_runtime.h>
#include <cstdint>

#define kB    32768
#define kT    276
#define kK    4416
#define kN    276

__device__ float g_h[(size_t)kB * kK];   // [B, T*2H] activations

// ---------------- Phase 1: bidirectional LSTM ----------------
__device__ __forceinline__ float sigm(float x) {
    return __fdividef(1.0f, 1.0f + __expf(-x));
}
__device__ __forceinline__ float tanh_acc(float x) {
    float e = __expf(-2.0f * fabsf(x));
    return copysignf(__fdividef(1.0f - e, 1.0f + e), x);
}

__global__ void __launch_bounds__(256) lstm_k(
    const float* __restrict__ x,
    const float* __restrict__ Wih_f, const float* __restrict__ Whh_f,
    const float* __restrict__ bih_f, const float* __restrict__ bhh_f,
    const float* __restrict__ Wih_b, const float* __restrict__ Whh_b,
    const float* __restrict__ bih_b, const float* __restrict__ bhh_b)
{
    __shared__ float s_whh[256], s_wih[64], s_b[32];
    const int tid = threadIdx.x;
    const int dir = blockIdx.y;
    const float* Whh = dir ? Whh_b : Whh_f;
    const float* Wih = dir ? Wih_b : Wih_f;
    s_whh[tid] = Whh[tid];
    if (tid < 64) s_wih[tid] = Wih[tid];
    if (tid < 32) s_b[tid] = (dir ? bih_b[tid] + bhh_b[tid] : bih_f[tid] + bhh_f[tid]);
    __syncthreads();

    const int b = blockIdx.x * 256 + tid;
    const float2* xp = reinterpret_cast<const float2*>(x) + (size_t)b * kT;
    int t = dir ? (kT - 1) : 0;
    const int dt = dir ? -1 : 1;
    float* hb = g_h + (size_t)b * kK + dir * 8;

    float h[8], c[8];
#pragma unroll
    for (int l = 0; l < 8; l++) { h[l] = 0.f; c[l] = 0.f; }

    float2 xv = xp[t];
    for (int s = 0; s < kT; ++s) {
        float2 xnext = xv;
        if (s + 1 < kT) xnext = xp[t + dt];
        float hn[8];
#pragma unroll
        for (int l = 0; l < 8; l++) {
            float ai = fmaf(xv.y, s_wih[2*l+1],      fmaf(xv.x, s_wih[2*l],      s_b[l]));
            float af = fmaf(xv.y, s_wih[2*(8+l)+1],  fmaf(xv.x, s_wih[2*(8+l)],  s_b[8+l]));
            float ag = fmaf(xv.y, s_wih[2*(16+l)+1], fmaf(xv.x, s_wih[2*(16+l)], s_b[16+l]));
            float ao = fmaf(xv.y, s_wih[2*(24+l)+1], fmaf(xv.x, s_wih[2*(24+l)], s_b[24+l]));
#pragma unroll
            for (int j = 0; j < 8; j++) {
                float hj = h[j];
                ai = fmaf(hj, s_whh[l*8+j],      ai);
                af = fmaf(hj, s_whh[(8+l)*8+j],  af);
                ag = fmaf(hj, s_whh[(16+l)*8+j], ag);
                ao = fmaf(hj, s_whh[(24+l)*8+j], ao);
            }
            float cn = fmaf(sigm(af), c[l], sigm(ai) * tanh_acc(ag));
            c[l] = cn;
            hn[l] = sigm(ao) * tanh_acc(cn);
        }
#pragma unroll
        for (int l = 0; l < 8; l++) h[l] = hn[l];
        float4* dst = reinterpret_cast<float4*>(hb + (size_t)t * 16);
        dst[0] = make_float4(hn[0], hn[1], hn[2], hn[3]);
        dst[1] = make_float4(hn[4], hn[5], hn[6], hn[7]);
        t += dt;
        xv = xnext;
    }
}

// ---------------- Phase 2: FC GEMM via mma.sync tf32 ----------------
// out[32768,276] = g_h[32768,4416] @ Wfc[276,4416]^T + bfc
// CTA tile M=128 x N=288(pad), 8 warps (2M x 4N), warp tile 64x72.
// Smem pitch 36 floats -> fragment LDS banks (4r+c): conflict-free.

#define ASTR 36
#define ABUF (128 * ASTR)          /* floats per A buffer */
#define BBUF (288 * ASTR)
#define NSTG 138                   /* 4416 / 32 */
#define FC_SMEM ((2 * ABUF + 2 * BBUF) * 4)

__device__ __forceinline__ uint32_t smem_u32(const void* p) {
    uint32_t a;
    asm("{ .reg .u64 t; cvta.to.shared.u64 t, %1; cvt.u32.u64 %0, t; }" : "=r"(a) : "l"(p));
    return a;
}
__device__ __forceinline__ void cpa16(uint32_t d, const void* s) {
    asm volatile("cp.async.cg.shared.global [%0], [%1], 16;" :: "r"(d), "l"(s));
}
__device__ __forceinline__ uint32_t f2tf(float f) {
    uint32_t u;
    asm("cvt.rna.tf32.f32 %0, %1;" : "=r"(u) : "f"(f));
    return u;
}
__device__ __forceinline__ void mma_tf32(float* d, const uint32_t* a, const uint32_t* b) {
    asm volatile(
        "mma.sync.aligned.m16n8k8.row.col.f32.tf32.tf32.f32 "
        "{%0,%1,%2,%3}, {%4,%5,%6,%7}, {%8,%9}, {%0,%1,%2,%3};"
        : "+f"(d[0]), "+f"(d[1]), "+f"(d[2]), "+f"(d[3])
        : "r"(a[0]), "r"(a[1]), "r"(a[2]), "r"(a[3]), "r"(b[0]), "r"(b[1]));
}

__global__ void __launch_bounds__(256, 1) fc_k(
    const float* __restrict__ Wfc, const float* __restrict__ bfc,
    float* __restrict__ out)
{
    extern __shared__ float sm[];
    float* sA = sm;                 // [2][128][36]
    float* sB = sm + 2 * ABUF;      // [2][288][36]

    const int tid = threadIdx.x;
    const int wid = tid >> 5, lid = tid & 31;
    const int wm = (wid & 1) * 64;         // warp M offset
    const int wn = (wid >> 1) * 72;        // warp N offset
    const int r  = lid >> 2, cc = lid & 3; // fragment row / col
    const size_t m0 = (size_t)blockIdx.x * 128;

    auto loadA = [&](int st, int buf) {
        const uint32_t dA = smem_u32(sA + buf * ABUF);
        const float* src = g_h + m0 * kK + st * 32;
#pragma unroll
        for (int i = 0; i < 4; i++) {
            int seg = tid + i * 256;                // < 1024
            int row = seg >> 3, ks = seg & 7;
            cpa16(dA + (row * ASTR + ks * 4) * 4, src + (size_t)row * kK + ks * 4);
        }
    };
    auto loadB = [&](int st, int buf) {
        const uint32_t dB = smem_u32(sB + buf * BBUF);
        const float* src = Wfc + st * 32;
#pragma unroll
        for (int i = 0; i < 9; i++) {
            int seg = tid + i * 256;
            if (seg < kN * 8) {                      // rows 0..275 only
                int row = seg >> 3, ks = seg & 7;
                cpa16(dB + (row * ASTR + ks * 4) * 4, src + (size_t)row * kK + ks * 4);
            }
        }
    };

    float acc[4][9][4];
#pragma unroll
    for (int mf = 0; mf < 4; mf++)
#pragma unroll
        for (int nf = 0; nf < 9; nf++)
#pragma unroll
            for (int q = 0; q < 4; q++) acc[mf][nf][q] = 0.f;

    loadA(0, 0); loadB(0, 0);
    asm volatile("cp.async.commit_group;");
    loadA(1, 1); loadB(1, 1);
    asm volatile("cp.async.commit_group;");

    for (int s = 0; s < NSTG; s++) {
        const int buf = s & 1;
        if (s + 1 < NSTG) asm volatile("cp.async.wait_group 1;");
        else              asm volatile("cp.async.wait_group 0;");
        __syncthreads();

        const float* A_ = sA + buf * ABUF + (wm + r) * ASTR;
        const float* B_ = sB + buf * BBUF + (wn + r) * ASTR;
#pragma unroll
        for (int kk = 0; kk < 4; kk++) {
            const int k0 = kk * 8 + cc;
            uint32_t a[4][4], bfr[9][2];
#pragma unroll
            for (int mf = 0; mf < 4; mf++) {
                const float* p = A_ + mf * 16 * ASTR + k0;
                a[mf][0] = f2tf(p[0]);
                a[mf][1] = f2tf(p[8 * ASTR]);
                a[mf][2] = f2tf(p[4]);
                a[mf][3] = f2tf(p[8 * ASTR + 4]);
            }
#pragma unroll
            for (int nf = 0; nf < 9; nf++) {
                const float* p = B_ + nf * 8 * ASTR + k0;
                bfr[nf][0] = f2tf(p[0]);
                bfr[nf][1] = f2tf(p[4]);
            }
#pragma unroll
            for (int mf = 0; mf < 4; mf++)
#pragma unroll
                for (int nf = 0; nf < 9; nf++)
                    mma_tf32(acc[mf][nf], a[mf], bfr[nf]);
        }
        __syncthreads();

        if (s + 2 < NSTG) {
            loadA(s + 2, buf); loadB(s + 2, buf);
            asm volatile("cp.async.commit_group;");
        }
    }

    // Epilogue: d0/d1 -> (row, n0/n0+1), d2/d3 -> (row+8, ...)
#pragma unroll
    for (int nf = 0; nf < 9; nf++) {
        const int n0 = wn + nf * 8 + cc * 2;
        if (n0 < kN) {
            const float b0 = bfc[n0], b1 = bfc[n0 + 1];
#pragma unroll
            for (int mf = 0; mf < 4; mf++) {
                const size_t mlo = m0 + wm + mf * 16 + r;
                float2 v0 = make_float2(acc[mf][nf][0] + b0, acc[mf][nf][1] + b1);
                float2 v1 = make_float2(acc[mf][nf][2] + b0, acc[mf][nf][3] + b1);
                *reinterpret_cast<float2*>(out + mlo * kN + n0)       = v0;
                *reinterpret_cast<float2*>(out + (mlo + 8) * kN + n0) = v1;
            }
        }
    }
}

extern "C" void kernel_launch(void* const* d_in, const int* in_sizes, int n_in,
                              void* d_out, int out_size) {
    const float* x     = (const float*)d_in[0];
    const float* Wih_f = (const float*)d_in[1];
    const float* Whh_f = (const float*)d_in[2];
    const float* bih_f = (const float*)d_in[3];
    const float* bhh_f = (const float*)d_in[4];
    const float* Wih_b = (const float*)d_in[5];
    const float* Whh_b = (const float*)d_in[6];
    const float* bih_b = (const float*)d_in[7];
    const float* bhh_b = (const float*)d_in[8];
    const float* Wfc   = (const float*)d_in[9];
    const float* bfc   = (const float*)d_in[10];
    float* out = (float*)d_out;

    static int smem_set = 0;
    if (!smem_set) {
        cudaFuncSetAttribute(fc_k, cudaFuncAttributeMaxDynamicSharedMemorySize, FC_SMEM);
        smem_set = 1;
    }

    lstm_k<<<dim3(kB / 256, 2), 256>>>(x, Wih_f, Whh_f, bih_f, bhh_f,
                                       Wih_b, Whh_b, bih_b, bhh_b);
    fc_k<<<kB / 128, 256, FC_SMEM>>>(Wfc, bfc, out);
}